// round 3
// baseline (speedup 1.0000x reference)
#include <cuda_runtime.h>
#include <cuda_bf16.h>

#define N_ATOMS 8192
#define NT 85
#define BINS 28
#define TILE 128
#define NTILES (N_ATOMS / TILE)   // 64
#define THREADS 256
#define LUT_SIZE (NT * NT * BINS) // 202300

// Fused (e0, e1) LUT: lut[(t1*NT+t2)*BINS + d] = (pot[..][d], pot[..][min(d+1,27)])
// 1.62 MB device global — rebuilt every launch (cheap, idempotent).
__device__ float2 g_lut[LUT_SIZE];
__device__ double g_sum;

__global__ void zero_accum_kernel() { g_sum = 0.0; }

__global__ void build_lut_kernel(const float* __restrict__ pot) {
    int idx = blockIdx.x * blockDim.x + threadIdx.x;
    if (idx < LUT_SIZE) {
        int d = idx % BINS;
        float e0 = pot[idx];
        float e1 = pot[(d == BINS - 1) ? idx : (idx + 1)];
        g_lut[idx] = make_float2(e0, e1);
    }
}

__global__ void finalize_kernel(float* __restrict__ out) {
    out[0] = (float)g_sum;
}

// One block per (ti, tj) tile pair with ti <= tj (blocks with ti > tj exit).
// Each thread owns one j-atom (in registers) and sweeps 64 i-atoms via SMEM
// broadcast. Diagonal tiles predicate on il < jl.
__global__ __launch_bounds__(THREADS)
void dfire_tile_kernel(const float* __restrict__ coords,
                       const int*  __restrict__ res_ids,
                       const int*  __restrict__ type_indices) {
    const int ti = blockIdx.x;
    const int tj = blockIdx.y;
    if (ti > tj) return;

    __shared__ float4 s_i[TILE];
    __shared__ float4 s_j[TILE];
    __shared__ double s_warp[THREADS / 32];

    const int tid = threadIdx.x;

    // Cooperative tile load: first 128 threads load i-tile, last 128 j-tile.
    {
        int local = tid & (TILE - 1);
        int base  = (tid < TILE) ? (ti * TILE) : (tj * TILE);
        int g     = base + local;
        float x = coords[g * 3 + 0];
        float y = coords[g * 3 + 1];
        float z = coords[g * 3 + 2];
        int packed = (res_ids[g] << 7) | type_indices[g];  // res<512, type<128
        float4 v = make_float4(x, y, z, __int_as_float(packed));
        if (tid < TILE) s_i[local] = v; else s_j[local] = v;
    }
    __syncthreads();

    // Register-resident j atom.
    const int jl = tid & (TILE - 1);
    const float4 aj = s_j[jl];
    const int   pj    = __float_as_int(aj.w);
    const int   jres  = pj >> 7;
    const int   jtype = pj & 127;
    const bool  offdiag = (ti < tj);

    const float2* __restrict__ lut = g_lut;

    float acc = 0.0f;
    int il = tid >> 7;  // 0 or 1; strides by 2 → covers all 128 i locals

#pragma unroll 4
    for (int k = 0; k < TILE / 2; ++k, il += 2) {
        float4 ai = s_i[il];  // warp-uniform broadcast
        float dx = ai.x - aj.x;
        float dy = ai.y - aj.y;
        float dz = ai.z - aj.z;
        float d2 = fmaf(dx, dx, fmaf(dy, dy, dz * dz));

        int   pi   = __float_as_int(ai.w);
        int   sep  = abs((pi >> 7) - jres);
        bool  ok   = (offdiag | (il < jl)) & (sep > 2) & (d2 < 384.1601f);

        if (ok) {
            float d  = sqrtf(d2) + 1e-8f;
            if (d < 19.6f) {
                float ds = d * (1.0f / 0.7f);
                float dsc = fminf(ds, 27.0f);
                int   d0 = (int)dsc;           // dsc >= 0 → trunc == floor
                float alpha = ds - (float)d0;
                int   itype = pi & 127;
                int   base  = (itype * NT + jtype) * BINS + d0;
                float2 e = __ldg(&lut[base]);
                acc += fmaf(alpha, e.y - e.x, e.x);
            }
        }
    }

    // Reduce: warp shuffle (fp32) → per-warp double → block double → atomic.
#pragma unroll
    for (int off = 16; off > 0; off >>= 1)
        acc += __shfl_xor_sync(0xFFFFFFFFu, acc, off);

    int lane = tid & 31;
    int wid  = tid >> 5;
    if (lane == 0) s_warp[wid] = (double)acc;
    __syncthreads();
    if (tid == 0) {
        double s = 0.0;
#pragma unroll
        for (int w = 0; w < THREADS / 32; ++w) s += s_warp[w];
        atomicAdd(&g_sum, s);
    }
}

extern "C" void kernel_launch(void* const* d_in, const int* in_sizes, int n_in,
                              void* d_out, int out_size) {
    // Input order (metadata): coords, pot_tensor, res_ids, type_indices, i_idx, j_idx
    const float* coords       = (const float*)d_in[0];
    const float* pot_tensor   = (const float*)d_in[1];
    const int*   res_ids      = (const int*)d_in[2];
    const int*   type_indices = (const int*)d_in[3];
    // i_idx / j_idx (d_in[4], d_in[5]) are deterministic triu indices — regenerated
    // implicitly by the tile decomposition; never read.
    (void)in_sizes; (void)n_in; (void)out_size;
    float* out = (float*)d_out;

    zero_accum_kernel<<<1, 1>>>();
    build_lut_kernel<<<(LUT_SIZE + 255) / 256, 256>>>(pot_tensor);

    dim3 grid(NTILES, NTILES);
    dfire_tile_kernel<<<grid, THREADS>>>(coords, res_ids, type_indices);

    finalize_kernel<<<1, 1>>>(out);
}